// round 7
// baseline (speedup 1.0000x reference)
#include <cuda_runtime.h>
#include <cstdint>

#define T_STEPS 2048
#define NB 32      // batch
#define NI 64      // input dim
#define NM 1024    // M == H
#define NBLK 144
#define NTHR 512

typedef unsigned long long u64;

// ---------------- device storage (static, no allocation) ----------------
__device__ __align__(16) float g_Vm1T[NM*NM];
__device__ __align__(16) float g_Vm2T[NM*NM];
__device__ __align__(16) float g_Pm2m1T[NM*NM];   // (Wm2@Vm1)^T
__device__ __align__(16) float g_Wh1T[NM*NM];
__device__ __align__(16) float g_Q1T[NM*NM];      // (Wmh1@Vm2)^T
__device__ __align__(16) float g_Q2T[NM*NM];      // (Wmh1@Wm2@Vm1)^T
__device__ __align__(16) float g_Win2T[NM*NM];
__device__ __align__(16) float g_Wh2T[NM*NM];
__device__ __align__(16) float g_Wmh2T[NM*NM];
__device__ __align__(16) float g_Wm1T[NI*NM];
__device__ __align__(16) float g_Pm2xT[NI*NM];    // (Wm2@Wm1)^T
__device__ __align__(16) float g_Win1effT[NI*NM]; // (Win1 + Wmh1@Wm2@Wm1)^T
__device__ __align__(16) float g_xT[T_STEPS*NI*NB];
__device__ __align__(16) float g_m1T[2][NM*NB];
__device__ __align__(16) float g_m2T[2][NM*NB];
__device__ __align__(16) float g_h1T[2][NM*NB];
__device__ __align__(16) float g_h2T[2][NM*NB];
__device__ __align__(16) float g_partial[9][NB*NM];

// monotone grid-barrier state (persists across graph replays by design)
__device__ unsigned g_count;
__device__ volatile unsigned g_gen;

#define FMA2(acc, a, b) asm("fma.rn.f32x2 %0, %1, %2, %0;" : "+l"(acc) : "l"(a), "l"(b))
#define ADD2(acc, b)    asm("add.rn.f32x2 %0, %0, %1;"     : "+l"(acc) : "l"(b))

// ---------------- precompute kernels ----------------
__global__ void transp_kernel(float* __restrict__ out, const float* __restrict__ in, int R, int C) {
    int idx = blockIdx.x * 256 + threadIdx.x;
    if (idx < R * C) {
        int r = idx / C, c = idx % C;
        out[(size_t)c * R + r] = in[idx];
    }
}

// out[k*N + n] = sum_j X[n*J + j] * (transY ? Y[k*J + j] : Y[j*K + k]) + (addC ? C[n*K + k] : 0)
__global__ void gemm_pre_kernel(const float* __restrict__ X, const float* __restrict__ Y,
                                const float* __restrict__ Cm, float* __restrict__ out,
                                int N, int J, int K, int transY, int addC) {
    __shared__ float As[64][17];
    __shared__ float Bs[16][68];
    int tx = threadIdx.x, ty = threadIdx.y;
    int tid = ty * 16 + tx;
    int n0 = blockIdx.x * 64, k0 = blockIdx.y * 64;
    float c[4][4];
    #pragma unroll
    for (int i = 0; i < 4; i++)
        #pragma unroll
        for (int l = 0; l < 4; l++) c[i][l] = 0.f;

    for (int jt = 0; jt < J; jt += 16) {
        for (int e = tid; e < 1024; e += 256) {
            int r = e >> 4, cc = e & 15;
            As[r][cc] = transY ? Y[(size_t)(k0 + r) * J + jt + cc]
                               : Y[(size_t)(jt + cc) * K + k0 + r];
        }
        for (int e = tid; e < 1024; e += 256) {
            int jj = e >> 6, nn = e & 63;
            Bs[jj][nn] = X[(size_t)(n0 + nn) * J + jt + jj];
        }
        __syncthreads();
        #pragma unroll
        for (int j = 0; j < 16; j++) {
            float a[4], b[4];
            #pragma unroll
            for (int i = 0; i < 4; i++) a[i] = As[ty * 4 + i][j];
            #pragma unroll
            for (int i = 0; i < 4; i++) b[i] = Bs[j][tx * 4 + i];
            #pragma unroll
            for (int i = 0; i < 4; i++)
                #pragma unroll
                for (int l = 0; l < 4; l++) c[i][l] += a[i] * b[l];
        }
        __syncthreads();
    }
    #pragma unroll
    for (int i = 0; i < 4; i++)
        #pragma unroll
        for (int l = 0; l < 4; l++) {
            int k = k0 + ty * 4 + i, n = n0 + tx * 4 + l;
            float v = c[i][l];
            if (addC) v += Cm[(size_t)n * K + k];
            out[(size_t)k * N + n] = v;
        }
}

__global__ void xtrans_kernel(const float* __restrict__ x) {
    int idx = blockIdx.x * 256 + threadIdx.x;
    if (idx < NB * T_STEPS * NI) {
        int b = idx >> 17;
        int r = idx & 131071;
        int tt = r >> 6;
        int i = r & 63;
        g_xT[tt * (NI * NB) + i * NB + b] = x[idx];
    }
}

__global__ void zero_states_kernel() {
    int i = blockIdx.x * 256 + threadIdx.x;
    if (i < 65536) ((float*)g_m1T)[i] = 0.f;
    else if (i < 131072) ((float*)g_m2T)[i - 65536] = 0.f;
    else if (i < 196608) ((float*)g_h1T)[i - 131072] = 0.f;
    else if (i < 262144) ((float*)g_h2T)[i - 196608] = 0.f;
}

// ---------------- persistent kernel ----------------
// 144 blocks x 512 threads, all co-resident (1 CTA/SM), software grid barrier.
// gemm: block = (mm, 64-col slice). 16 warps = 4 (n,b)-slots x 4-way k-split.
// warp: 32 n (lane) x 16 b -> 8 f32x2 accumulators, 256 k per warp.
__device__ __forceinline__ void grid_sync(unsigned target) {
    __syncthreads();
    if (threadIdx.x == 0) {
        __threadfence();
        unsigned a = atomicAdd(&g_count, 1) + 1;
        if (a == target * (unsigned)NBLK) {
            __threadfence();
            g_gen = target;
        } else {
            while (g_gen < target) { }
            __threadfence();
        }
    }
    __syncthreads();
}

extern "C" __global__ void __launch_bounds__(NTHR, 1)
persist_kernel(const float* __restrict__ b1, const float* __restrict__ b2,
               float* __restrict__ out) {
    extern __shared__ float sA[];   // 1024*32 floats = 128KB
    __shared__ unsigned s_base;

    const int tid  = threadIdx.x;
    const int w    = tid >> 5, lane = tid & 31;
    const int slot = w & 3;         // 2 n-groups x 2 b-groups
    const int kq   = w >> 2;        // k quarter (0..3)
    const int mm   = blockIdx.x >> 4;
    const int blk  = blockIdx.x & 15;
    const int n    = blk * 64 + (slot >> 1) * 32 + lane;
    const int b0   = (slot & 1) * 16;

    if (tid == 0) s_base = g_gen;
    __syncthreads();
    unsigned bar = s_base;

    for (int t = 0; t <= T_STEPS; t++) {
        const int cur = t & 1;
        const float *A, *W, *Wx = 0;
        switch (mm) {
            case 0: A = g_m1T[cur]; W = g_Vm1T;   Wx = g_Wm1T;     break;
            case 1: A = g_m2T[cur]; W = g_Vm2T;   Wx = g_Pm2xT;    break;
            case 2: A = g_m1T[cur]; W = g_Pm2m1T;                  break;
            case 3: A = g_h1T[cur]; W = g_Wh1T;   Wx = g_Win1effT; break;
            case 4: A = g_m2T[cur]; W = g_Q1T;                     break;
            case 5: A = g_m1T[cur]; W = g_Q2T;                     break;
            case 6: A = g_h1T[cur]; W = g_Win2T;                   break;
            case 7: A = g_h2T[cur]; W = g_Wh2T;                    break;
            default:A = g_m2T[cur]; W = g_Wmh2T;                   break;
        }

        u64 acc[8];
        #pragma unroll
        for (int i = 0; i < 8; i++) acc[i] = 0ull;

        // ---- x contribution (block-uniform branch) ----
        if (Wx) {
            int tt = t < T_STEPS ? t : T_STEPS - 1;
            const float* xs = g_xT + (size_t)tt * (NI * NB);
            for (int i = tid; i < NI * NB; i += NTHR) sA[i] = xs[i];
            __syncthreads();
            const float* wp = Wx + (size_t)(kq * 16) * NM + n;
            #pragma unroll 4
            for (int kk = 0; kk < 16; kk++) {
                float wv = __ldg(wp + (size_t)kk * NM);
                uint32_t wu = __float_as_uint(wv);
                u64 w2; asm("mov.b64 %0, {%1,%2};" : "=l"(w2) : "r"(wu), "r"(wu));
                const ulonglong2* ap = (const ulonglong2*)(sA + (kq * 16 + kk) * 32 + b0);
                ulonglong2 a0 = ap[0], a1 = ap[1], a2 = ap[2], a3 = ap[3];
                FMA2(acc[0], w2, a0.x); FMA2(acc[1], w2, a0.y);
                FMA2(acc[2], w2, a1.x); FMA2(acc[3], w2, a1.y);
                FMA2(acc[4], w2, a2.x); FMA2(acc[5], w2, a2.y);
                FMA2(acc[6], w2, a3.x); FMA2(acc[7], w2, a3.y);
            }
            __syncthreads();
        }

        // ---- stage full A state (128KB) into smem ----
        {
            const float4* src = (const float4*)A;
            float4* dst = (float4*)sA;
            #pragma unroll
            for (int i = 0; i < (NM * NB / 4) / NTHR; i++)
                dst[tid + i * NTHR] = src[tid + i * NTHR];
        }
        __syncthreads();

        // ---- main 256-k loop ----
        {
            const float* wp = W + (size_t)(kq * 256) * NM + n;
            const float* sa = sA + (kq * 256) * 32 + b0;
            #pragma unroll 4
            for (int k = 0; k < 256; k++) {
                float wv = __ldg(wp + (size_t)k * NM);
                uint32_t wu = __float_as_uint(wv);
                u64 w2; asm("mov.b64 %0, {%1,%2};" : "=l"(w2) : "r"(wu), "r"(wu));
                const ulonglong2* ap = (const ulonglong2*)(sa + k * 32);
                ulonglong2 a0 = ap[0], a1 = ap[1], a2 = ap[2], a3 = ap[3];
                FMA2(acc[0], w2, a0.x); FMA2(acc[1], w2, a0.y);
                FMA2(acc[2], w2, a1.x); FMA2(acc[3], w2, a1.y);
                FMA2(acc[4], w2, a2.x); FMA2(acc[5], w2, a2.y);
                FMA2(acc[6], w2, a3.x); FMA2(acc[7], w2, a3.y);
            }
        }

        // ---- cross-kq reduction via smem ----
        __syncthreads();
        u64* R = (u64*)sA;
        if (kq > 0) {
            int base = (((kq - 1) * 4 + slot) * 32 + lane) * 8;
            #pragma unroll
            for (int i = 0; i < 8; i++) R[base + i] = acc[i];
        }
        __syncthreads();
        if (kq == 0) {
            #pragma unroll
            for (int q = 1; q < 4; q++) {
                int base = (((q - 1) * 4 + slot) * 32 + lane) * 8;
                #pragma unroll
                for (int i = 0; i < 8; i++) ADD2(acc[i], R[base + i]);
            }
            float* p = g_partial[mm] + (size_t)b0 * NM + n;
            #pragma unroll
            for (int i = 0; i < 8; i++) {
                uint32_t lo, hi;
                asm("mov.b64 {%0,%1}, %2;" : "=r"(lo), "=r"(hi) : "l"(acc[i]));
                p[(size_t)(2 * i) * NM]     = __uint_as_float(lo);
                p[(size_t)(2 * i + 1) * NM] = __uint_as_float(hi);
            }
        }

        grid_sync(++bar);

        // ---- combine phase: blocks 0..127 (4 kinds x 32 n-tiles) ----
        if (blockIdx.x < 128) {
            const int kind = blockIdx.x >> 5;     // 0:m1 1:m2 2:h1 3:h2
            const int n0c  = (blockIdx.x & 31) * 32;
            const int nxt  = cur ^ 1;
            float* tile = sA;                     // 32x33
            if (tid < 256) {
                int cw = tid >> 5, cl = tid & 31;
                #pragma unroll
                for (int rr = 0; rr < 4; rr++) {
                    int b = cw * 4 + rr;
                    int nn = n0c + cl;
                    size_t off = (size_t)b * NM + nn;
                    float v;
                    if (kind == 0)      v = g_partial[0][off];
                    else if (kind == 1) v = g_partial[1][off] + g_partial[2][off];
                    else if (kind == 2) v = tanhf(g_partial[3][off] + g_partial[4][off] + g_partial[5][off] + b1[nn]);
                    else                v = tanhf(g_partial[6][off] + g_partial[7][off] + g_partial[8][off] + b2[nn]);
                    tile[cl * 33 + b] = v;
                }
            }
            __syncthreads();
            if (tid < 256) {
                int cw = tid >> 5, cl = tid & 31;
                #pragma unroll
                for (int rr = 0; rr < 4; rr++) {
                    int nn = cw * 4 + rr;
                    int ng = n0c + nn;
                    float v = tile[nn * 33 + cl];
                    int o = ng * NB + cl;
                    if (kind == 0)      g_m1T[nxt][o] = v;
                    else if (kind == 1) g_m2T[nxt][o] = v;
                    else if (kind == 2) g_h1T[nxt][o] = 0.5f * g_h1T[cur][o] + 0.5f * v;
                    else if (t >= 1) {
                        float h2v = 0.5f * g_h2T[cur][o] + 0.5f * v;
                        g_h2T[nxt][o] = h2v;
                        out[(size_t)cl * T_STEPS * NM + (size_t)(t - 1) * NM + ng] = h2v;
                    }
                }
            }
        }

        grid_sync(++bar);
    }
}

// ---------------- launch ----------------
extern "C" void kernel_launch(void* const* d_in, const int* in_sizes, int n_in,
                              void* d_out, int out_size) {
    const float* x    = (const float*)d_in[0];
    const float* Wm1  = (const float*)d_in[1];
    const float* Vm1  = (const float*)d_in[2];
    const float* Wm2  = (const float*)d_in[3];
    const float* Vm2  = (const float*)d_in[4];
    const float* Win1 = (const float*)d_in[5];
    const float* Wh1  = (const float*)d_in[6];
    const float* Wmh1 = (const float*)d_in[7];
    const float* b1   = (const float*)d_in[8];
    const float* Win2 = (const float*)d_in[9];
    const float* Wh2  = (const float*)d_in[10];
    const float* Wmh2 = (const float*)d_in[11];
    const float* b2   = (const float*)d_in[12];
    float* out = (float*)d_out;

    float *pVm1T, *pVm2T, *pWh1T, *pWin2T, *pWh2T, *pWmh2T, *pWm1T;
    float *pPm2m1T, *pQ1T, *pQ2T, *pPm2xT, *pWin1effT;
    cudaGetSymbolAddress((void**)&pVm1T,  g_Vm1T);
    cudaGetSymbolAddress((void**)&pVm2T,  g_Vm2T);
    cudaGetSymbolAddress((void**)&pWh1T,  g_Wh1T);
    cudaGetSymbolAddress((void**)&pWin2T, g_Win2T);
    cudaGetSymbolAddress((void**)&pWh2T,  g_Wh2T);
    cudaGetSymbolAddress((void**)&pWmh2T, g_Wmh2T);
    cudaGetSymbolAddress((void**)&pWm1T,  g_Wm1T);
    cudaGetSymbolAddress((void**)&pPm2m1T, g_Pm2m1T);
    cudaGetSymbolAddress((void**)&pQ1T,    g_Q1T);
    cudaGetSymbolAddress((void**)&pQ2T,    g_Q2T);
    cudaGetSymbolAddress((void**)&pPm2xT,  g_Pm2xT);
    cudaGetSymbolAddress((void**)&pWin1effT, g_Win1effT);

    const int TB = 256;
    int nBig = (NM * NM + TB - 1) / TB;
    transp_kernel<<<nBig, TB>>>(pVm1T,  Vm1,  NM, NM);
    transp_kernel<<<nBig, TB>>>(pVm2T,  Vm2,  NM, NM);
    transp_kernel<<<nBig, TB>>>(pWh1T,  Wh1,  NM, NM);
    transp_kernel<<<nBig, TB>>>(pWin2T, Win2, NM, NM);
    transp_kernel<<<nBig, TB>>>(pWh2T,  Wh2,  NM, NM);
    transp_kernel<<<nBig, TB>>>(pWmh2T, Wmh2, NM, NM);
    transp_kernel<<<(NM * NI + TB - 1) / TB, TB>>>(pWm1T, Wm1, NM, NI);

    dim3 gblock(16, 16);
    dim3 ggridMM(NM / 64, NM / 64);
    dim3 ggridI (NM / 64, NI / 64);
    gemm_pre_kernel<<<ggridMM, gblock>>>(Wm2,  Vm1,     nullptr, pPm2m1T,   NM, NM, NM, 0, 0);
    gemm_pre_kernel<<<ggridMM, gblock>>>(Wmh1, Vm2,     nullptr, pQ1T,      NM, NM, NM, 0, 0);
    gemm_pre_kernel<<<ggridMM, gblock>>>(Wmh1, pPm2m1T, nullptr, pQ2T,      NM, NM, NM, 1, 0);
    gemm_pre_kernel<<<ggridI,  gblock>>>(Wm2,  Wm1,     nullptr, pPm2xT,    NM, NM, NI, 0, 0);
    gemm_pre_kernel<<<ggridI,  gblock>>>(Wmh1, pPm2xT,  Win1,    pWin1effT, NM, NM, NI, 1, 1);

    xtrans_kernel<<<(NB * T_STEPS * NI + TB - 1) / TB, TB>>>(x);
    zero_states_kernel<<<1024, TB>>>();

    cudaFuncSetAttribute(persist_kernel,
                         cudaFuncAttributeMaxDynamicSharedMemorySize, NM * NB * 4);
    persist_kernel<<<NBLK, NTHR, NM * NB * 4>>>(b1, b2, out);
}

// round 8
// speedup vs baseline: 1.4683x; 1.4683x over previous
#include <cuda_runtime.h>
#include <cstdint>

#define T_STEPS 2048
#define NB 32      // batch
#define NI 64      // input dim
#define NM 1024    // M == H
#define NBLK 144
#define NTHR 512

typedef unsigned long long u64;

// ---------------- device storage (static, no allocation) ----------------
__device__ __align__(16) float g_Vm1T[NM*NM];
__device__ __align__(16) float g_Vm2T[NM*NM];
__device__ __align__(16) float g_Pm2m1T[NM*NM];   // (Wm2@Vm1)^T
__device__ __align__(16) float g_Wh1T[NM*NM];
__device__ __align__(16) float g_Q1T[NM*NM];      // (Wmh1@Vm2)^T
__device__ __align__(16) float g_Q2T[NM*NM];      // (Wmh1@Wm2@Vm1)^T
__device__ __align__(16) float g_Win2T[NM*NM];
__device__ __align__(16) float g_Wh2T[NM*NM];
__device__ __align__(16) float g_Wmh2T[NM*NM];
__device__ __align__(16) float g_Wm1T[NI*NM];
__device__ __align__(16) float g_Pm2xT[NI*NM];    // (Wm2@Wm1)^T
__device__ __align__(16) float g_Win1effT[NI*NM]; // (Win1 + Wmh1@Wm2@Wm1)^T
__device__ __align__(16) float g_xT[T_STEPS*NI*NB];
// states, layout [n][b]
__device__ __align__(16) float g_m1T[2][NM*NB];
__device__ __align__(16) float g_m2T[2][NM*NB];
__device__ __align__(16) float g_h1T[2][NM*NB];
__device__ __align__(16) float g_h2T[2][NM*NB];
// partial products, layout [n][b]
__device__ __align__(16) float g_partial[9][NM*NB];

// monotone grid-barrier state (persists across graph replays by design)
__device__ unsigned g_count;
__device__ unsigned g_gen;

#define FMA2(acc, a, b) asm("fma.rn.f32x2 %0, %1, %2, %0;" : "+l"(acc) : "l"(a), "l"(b))
#define ADD2(acc, b)    asm("add.rn.f32x2 %0, %0, %1;"     : "+l"(acc) : "l"(b))
#define PACK2(w2, wu)   asm("mov.b64 %0, {%1, %1};"        : "=l"(w2)  : "r"(wu))

__device__ __forceinline__ unsigned ld_acq(const unsigned* p) {
    unsigned v;
    asm volatile("ld.global.acquire.gpu.u32 %0, [%1];" : "=r"(v) : "l"(p) : "memory");
    return v;
}

// ---------------- setup kernels (exactly 5 launches before persist) ----------------

// launch 0: all 7 transposes. grid (4096, 7)
__global__ void transp_all_kernel(const float* __restrict__ Vm1, const float* __restrict__ Vm2,
                                  const float* __restrict__ Wh1, const float* __restrict__ Win2,
                                  const float* __restrict__ Wh2, const float* __restrict__ Wmh2,
                                  const float* __restrict__ Wm1) {
    const float* in; float* out; int C = NM;
    switch (blockIdx.y) {
        case 0: in = Vm1;  out = g_Vm1T;  break;
        case 1: in = Vm2;  out = g_Vm2T;  break;
        case 2: in = Wh1;  out = g_Wh1T;  break;
        case 3: in = Win2; out = g_Win2T; break;
        case 4: in = Wh2;  out = g_Wh2T;  break;
        case 5: in = Wmh2; out = g_Wmh2T; break;
        default:in = Wm1;  out = g_Wm1T;  C = NI; break;
    }
    int idx = blockIdx.x * 256 + threadIdx.x;
    if (idx < NM * C) {
        int r = idx / C, c = idx % C;
        out[(size_t)c * NM + r] = in[idx];
    }
}

// out[k*N + n] = sum_j X[n*J + j] * (transY ? Y[k*J + j] : Y[j*K + k]) + (addC ? C[n*K + k] : 0)
__device__ __forceinline__ void gemm_pre_body(const float* __restrict__ X, const float* __restrict__ Y,
                                              const float* __restrict__ Cm, float* __restrict__ out,
                                              int N, int J, int K, int transY, int addC) {
    __shared__ float As[64][17];
    __shared__ float Bs[16][68];
    int tx = threadIdx.x, ty = threadIdx.y;
    int tid = ty * 16 + tx;
    int n0 = blockIdx.x * 64, k0 = blockIdx.y * 64;
    float c[4][4];
    #pragma unroll
    for (int i = 0; i < 4; i++)
        #pragma unroll
        for (int l = 0; l < 4; l++) c[i][l] = 0.f;

    for (int jt = 0; jt < J; jt += 16) {
        for (int e = tid; e < 1024; e += 256) {
            int r = e >> 4, cc = e & 15;
            As[r][cc] = transY ? Y[(size_t)(k0 + r) * J + jt + cc]
                               : Y[(size_t)(jt + cc) * K + k0 + r];
        }
        for (int e = tid; e < 1024; e += 256) {
            int jj = e >> 6, nn = e & 63;
            Bs[jj][nn] = X[(size_t)(n0 + nn) * J + jt + jj];
        }
        __syncthreads();
        #pragma unroll
        for (int j = 0; j < 16; j++) {
            float a[4], b[4];
            #pragma unroll
            for (int i = 0; i < 4; i++) a[i] = As[ty * 4 + i][j];
            #pragma unroll
            for (int i = 0; i < 4; i++) b[i] = Bs[j][tx * 4 + i];
            #pragma unroll
            for (int i = 0; i < 4; i++)
                #pragma unroll
                for (int l = 0; l < 4; l++) c[i][l] += a[i] * b[l];
        }
        __syncthreads();
    }
    #pragma unroll
    for (int i = 0; i < 4; i++)
        #pragma unroll
        for (int l = 0; l < 4; l++) {
            int k = k0 + ty * 4 + i, n = n0 + tx * 4 + l;
            float v = c[i][l];
            if (addC) v += Cm[(size_t)n * K + k];
            out[(size_t)k * N + n] = v;
        }
}

// launch 1: wave 1 (independent products). grid (16, 16, 3)
__global__ void pre_wave1_kernel(const float* __restrict__ Wm2, const float* __restrict__ Vm1,
                                 const float* __restrict__ Wmh1, const float* __restrict__ Vm2,
                                 const float* __restrict__ Wm1) {
    if (blockIdx.z == 0)      gemm_pre_body(Wm2,  Vm1, nullptr, g_Pm2m1T, NM, NM, NM, 0, 0);
    else if (blockIdx.z == 1) gemm_pre_body(Wmh1, Vm2, nullptr, g_Q1T,    NM, NM, NM, 0, 0);
    else { if (blockIdx.y > 0) return;
           gemm_pre_body(Wm2,  Wm1, nullptr, g_Pm2xT,  NM, NM, NI, 0, 0); }
}

// launch 2: wave 2 (depends on wave 1). grid (16, 16, 2)
__global__ void pre_wave2_kernel(const float* __restrict__ Wmh1, const float* __restrict__ Win1) {
    if (blockIdx.z == 0)      gemm_pre_body(Wmh1, g_Pm2m1T, nullptr, g_Q2T,     NM, NM, NM, 1, 0);
    else { if (blockIdx.y > 0) return;
           gemm_pre_body(Wmh1, g_Pm2xT, Win1, g_Win1effT, NM, NM, NI, 1, 1); }
}

// launch 3: x[b][t][i] -> g_xT[t][i][b]
__global__ void xtrans_kernel(const float* __restrict__ x) {
    int idx = blockIdx.x * 256 + threadIdx.x;
    if (idx < NB * T_STEPS * NI) {
        int b = idx >> 17;
        int r = idx & 131071;
        int tt = r >> 6;
        int i = r & 63;
        g_xT[tt * (NI * NB) + i * NB + b] = x[idx];
    }
}

// launch 4: zero both state buffers
__global__ void zero_states_kernel() {
    int i = blockIdx.x * 256 + threadIdx.x;
    if (i < 65536) ((float*)g_m1T)[i] = 0.f;
    else if (i < 131072) ((float*)g_m2T)[i - 65536] = 0.f;
    else if (i < 196608) ((float*)g_h1T)[i - 131072] = 0.f;
    else if (i < 262144) ((float*)g_h2T)[i - 196608] = 0.f;
}

// ---------------- persistent kernel ----------------
// 144 blocks x 512 threads (1 CTA/SM). Block = (mm, 64-n slice).
// 16 warps = 16 k-quarters (64 k each). Warp: 64 n (2 per lane) x 32 b.
// acc = 2 n x 16 b-pairs = 32 f32x2. Weights via LDG.64, depth-4 register prefetch.
__device__ __forceinline__ void grid_sync(unsigned target) {
    __syncthreads();
    if (threadIdx.x == 0) {
        __threadfence();
        unsigned a = atomicAdd(&g_count, 1) + 1;
        if (a == target * (unsigned)NBLK) {
            __threadfence();
            g_gen = target;   // plain store after fence
        } else {
            while (ld_acq(&g_gen) < target) { }
        }
    }
    __syncthreads();
}

// one k-step: 8 broadcast LDS.128 (32 b) + 32 FFMA2 into acc[0..31]
__device__ __forceinline__ void fma_step(u64* acc, const float* saRow, float2 wv) {
    uint32_t wxu = __float_as_uint(wv.x), wyu = __float_as_uint(wv.y);
    u64 wa, wb;
    PACK2(wa, wxu);
    PACK2(wb, wyu);
    const ulonglong2* ap = (const ulonglong2*)saRow;
    #pragma unroll
    for (int h = 0; h < 2; h++) {
        ulonglong2 q0 = ap[h*4+0], q1 = ap[h*4+1], q2 = ap[h*4+2], q3 = ap[h*4+3];
        int o = h * 8;
        FMA2(acc[o+0], wa, q0.x); FMA2(acc[16+o+0], wb, q0.x);
        FMA2(acc[o+1], wa, q0.y); FMA2(acc[16+o+1], wb, q0.y);
        FMA2(acc[o+2], wa, q1.x); FMA2(acc[16+o+2], wb, q1.x);
        FMA2(acc[o+3], wa, q1.y); FMA2(acc[16+o+3], wb, q1.y);
        FMA2(acc[o+4], wa, q2.x); FMA2(acc[16+o+4], wb, q2.x);
        FMA2(acc[o+5], wa, q2.y); FMA2(acc[16+o+5], wb, q2.y);
        FMA2(acc[o+6], wa, q3.x); FMA2(acc[16+o+6], wb, q3.x);
        FMA2(acc[o+7], wa, q3.y); FMA2(acc[16+o+7], wb, q3.y);
    }
}

extern "C" __global__ void __launch_bounds__(NTHR, 1)
persist_kernel(const float* __restrict__ b1, const float* __restrict__ b2,
               float* __restrict__ out) {
    extern __shared__ float sA[];   // 128 KB
    __shared__ unsigned s_base;

    const int tid  = threadIdx.x;
    const int w    = tid >> 5, lane = tid & 31;
    const int kq   = w;                 // 0..15
    const int mm   = blockIdx.x >> 4;
    const int blk  = blockIdx.x & 15;

    if (tid == 0) s_base = g_gen;
    __syncthreads();
    unsigned bar = s_base;

    for (int t = 0; t <= T_STEPS; t++) {
        const int cur = t & 1;
        const float *A, *W, *Wx = 0;
        switch (mm) {
            case 0: A = g_m1T[cur]; W = g_Vm1T;   Wx = g_Wm1T;     break;
            case 1: A = g_m2T[cur]; W = g_Vm2T;   Wx = g_Pm2xT;    break;
            case 2: A = g_m1T[cur]; W = g_Pm2m1T;                  break;
            case 3: A = g_h1T[cur]; W = g_Wh1T;   Wx = g_Win1effT; break;
            case 4: A = g_m2T[cur]; W = g_Q1T;                     break;
            case 5: A = g_m1T[cur]; W = g_Q2T;                     break;
            case 6: A = g_h1T[cur]; W = g_Win2T;                   break;
            case 7: A = g_h2T[cur]; W = g_Wh2T;                    break;
            default:A = g_m2T[cur]; W = g_Wmh2T;                   break;
        }

        u64 acc[32];
        #pragma unroll
        for (int i = 0; i < 32; i++) acc[i] = 0ull;

        // ---- x contribution (block-uniform branch): 4 k per warp ----
        if (Wx) {
            int tt = t < T_STEPS ? t : T_STEPS - 1;
            const float* xs = g_xT + (size_t)tt * (NI * NB);
            for (int i = tid; i < NI * NB; i += NTHR) sA[i] = xs[i];
            __syncthreads();
            const float2* xp = (const float2*)Wx + blk * 32 + lane;
            #pragma unroll
            for (int u = 0; u < 4; u++) {
                int kk = kq * 4 + u;
                float2 wv = __ldg(xp + (size_t)kk * 512);
                fma_step(acc, sA + kk * 32, wv);
            }
            __syncthreads();
        }

        // ---- stage full A state (128 KB) into smem ----
        {
            const float4* src = (const float4*)A;
            float4* dst = (float4*)sA;
            #pragma unroll
            for (int i = 0; i < (NM * NB / 4) / NTHR; i++)
                dst[tid + i * NTHR] = src[tid + i * NTHR];
        }
        __syncthreads();

        // ---- main 64-k loop, depth-4 register prefetch on weights ----
        {
            const float2* wp2 = (const float2*)W + (size_t)(kq * 64) * 512 + blk * 32 + lane;
            const float*  saw = sA + (kq * 64) * 32;
            float2 pf[4];
            #pragma unroll
            for (int u = 0; u < 4; u++) pf[u] = __ldg(wp2 + (size_t)u * 512);
            for (int kc = 0; kc < 64; kc += 4) {
                #pragma unroll
                for (int u = 0; u < 4; u++) {
                    float2 wv = pf[u];
                    pf[u] = __ldg(wp2 + (size_t)(((kc + 4 + u) & 63)) * 512);
                    fma_step(acc, saw + (kc + u) * 32, wv);
                }
            }
        }

        // ---- cross-kq reduction: rotated smem layout, pairwise tree ----
        __syncthreads();   // all warps done reading sA as A
        u64* Rsm = (u64*)sA;
        {
            int base = (w * 32 + lane) * 32;
            #pragma unroll
            for (int a = 0; a < 32; a++)
                Rsm[base + ((a + lane) & 31)] = acc[a];
        }
        __syncthreads();
        {
            u64* pout = (u64*)(g_partial[mm]) + (size_t)blk * 1024;
            #pragma unroll
            for (int r = 0; r < 2; r++) {
                int o  = tid * 2 + r;           // 0..1023: n_loc*16 + bpair
                int nl = o >> 4, bp = o & 15;
                int ls = nl >> 1;
                int a  = ((nl & 1) << 4) + bp;
                int idx = ls * 32 + ((a + ls) & 31);
                u64 v[16];
                #pragma unroll
                for (int q = 0; q < 16; q++) v[q] = Rsm[q * 1024 + idx];
                #pragma unroll
                for (int st = 8; st >= 1; st >>= 1)
                    #pragma unroll
                    for (int q = 0; q < 8; q++)
                        if (q < st) ADD2(v[q], v[q + st]);
                pout[o] = v[0];
            }
        }

        grid_sync(++bar);

        // ---- combine: blocks 0..127 (4 kinds x 32 n-tiles), [n][b] layout ----
        const int kind = blockIdx.x >> 5;
        const int n0c  = (blockIdx.x & 31) * 32;
        const int nxt  = cur ^ 1;
        float* tile = sA;                  // 32 x 33 (kind 3 only)
        if (blockIdx.x < 128 && tid < 256) {
            int cw = tid >> 5, cl = tid & 31;      // cl = batch
            #pragma unroll
            for (int rr = 0; rr < 4; rr++) {
                int n = n0c + cw * 4 + rr;
                int off = n * NB + cl;
                if (kind == 0) {
                    g_m1T[nxt][off] = g_partial[0][off];
                } else if (kind == 1) {
                    g_m2T[nxt][off] = g_partial[1][off] + g_partial[2][off];
                } else if (kind == 2) {
                    float v = tanhf(g_partial[3][off] + g_partial[4][off] + g_partial[5][off] + b1[n]);
                    g_h1T[nxt][off] = 0.5f * g_h1T[cur][off] + 0.5f * v;
                } else {
                    float v = tanhf(g_partial[6][off] + g_partial[7][off] + g_partial[8][off] + b2[n]);
                    if (t >= 1) {
                        float h2v = 0.5f * g_h2T[cur][off] + 0.5f * v;
                        g_h2T[nxt][off] = h2v;
                        tile[(n - n0c) * 33 + cl] = h2v;
                    }
                }
            }
        }
        __syncthreads();
        if (blockIdx.x < 128 && tid < 256 && kind == 3 && t >= 1) {
            int cw = tid >> 5, cl = tid & 31;      // cl = n offset now
            #pragma unroll
            for (int rr = 0; rr < 4; rr++) {
                int b = cw * 4 + rr;
                out[(size_t)b * T_STEPS * NM + (size_t)(t - 1) * NM + n0c + cl] = tile[cl * 33 + b];
            }
        }

        grid_sync(++bar);
    }
}

// ---------------- launch ----------------
extern "C" void kernel_launch(void* const* d_in, const int* in_sizes, int n_in,
                              void* d_out, int out_size) {
    const float* x    = (const float*)d_in[0];
    const float* Wm1  = (const float*)d_in[1];
    const float* Vm1  = (const float*)d_in[2];
    const float* Wm2  = (const float*)d_in[3];
    const float* Vm2  = (const float*)d_in[4];
    const float* Win1 = (const float*)d_in[5];
    const float* Wh1  = (const float*)d_in[6];
    const float* Wmh1 = (const float*)d_in[7];
    const float* b1   = (const float*)d_in[8];
    const float* Win2 = (const float*)d_in[9];
    const float* Wh2  = (const float*)d_in[10];
    const float* Wmh2 = (const float*)d_in[11];
    const float* b2   = (const float*)d_in[12];
    float* out = (float*)d_out;

    // exactly 5 setup launches so ncu (-s 5 -c 1) captures persist_kernel
    transp_all_kernel<<<dim3(4096, 7), 256>>>(Vm1, Vm2, Wh1, Win2, Wh2, Wmh2, Wm1);
    pre_wave1_kernel<<<dim3(16, 16, 3), dim3(16, 16)>>>(Wm2, Vm1, Wmh1, Vm2, Wm1);
    pre_wave2_kernel<<<dim3(16, 16, 2), dim3(16, 16)>>>(Wmh1, Win1);
    xtrans_kernel<<<(NB * T_STEPS * NI + 255) / 256, 256>>>(x);
    zero_states_kernel<<<1024, 256>>>();

    cudaFuncSetAttribute(persist_kernel,
                         cudaFuncAttributeMaxDynamicSharedMemorySize, NM * NB * 4);
    persist_kernel<<<NBLK, NTHR, NM * NB * 4>>>(b1, b2, out);
}